// round 9
// baseline (speedup 1.0000x reference)
#include <cuda_runtime.h>
#include <cstdint>

// Problem constants (match reference)
#define B_DIM 16
#define N_DIM 2048
#define S_DIM 4096
#define D_DIM 128
#define NNZ_DIM 1048576
#define ROWS (B_DIM * N_DIM)   // 32768 output rows

// ---------------------------------------------------------------------------
// Scratch (static __device__ — no allocations allowed)
// ---------------------------------------------------------------------------
__device__ int g_count[ROWS];
__device__ int g_offset[ROWS];
__device__ int g_cursor[ROWS];
__device__ unsigned long long g_sorted[NNZ_DIM];   // packed (val<<32 | tok), 8 MB

// ---------------------------------------------------------------------------
// Phase 0: zero the row counters (must run every graph replay)
// ---------------------------------------------------------------------------
__global__ void reset_kernel() {
    int i = blockIdx.x * blockDim.x + threadIdx.x;
    if (i < ROWS) g_count[i] = 0;
}

// ---------------------------------------------------------------------------
// Phase 1: histogram of destination rows
// ---------------------------------------------------------------------------
__global__ void __launch_bounds__(256)
hist_kernel(const int* __restrict__ mask_batch,
            const int* __restrict__ mask_node) {
    int i = blockIdx.x * blockDim.x + threadIdx.x;
    if (i >= NNZ_DIM) return;
    int row = __ldg(mask_batch + i) * N_DIM + __ldg(mask_node + i);
    atomicAdd(&g_count[row], 1);
}

// ---------------------------------------------------------------------------
// Phase 2: exclusive prefix sum over 32768 counts (single CTA, 1024 threads,
// 32 elements serial per thread + Hillis-Steele block scan of thread totals)
// ---------------------------------------------------------------------------
__global__ void __launch_bounds__(1024)
scan_kernel() {
    __shared__ int sm[1024];
    const int t = threadIdx.x;
    const int base = t * 32;

    int local[32];
    int sum = 0;
    #pragma unroll
    for (int j = 0; j < 32; j++) {
        local[j] = sum;
        sum += g_count[base + j];
    }

    sm[t] = sum;
    __syncthreads();
    // inclusive Hillis-Steele scan
    for (int off = 1; off < 1024; off <<= 1) {
        int v = (t >= off) ? sm[t - off] : 0;
        __syncthreads();
        sm[t] += v;
        __syncthreads();
    }
    const int excl = sm[t] - sum;   // exclusive prefix of this thread's chunk

    #pragma unroll
    for (int j = 0; j < 32; j++) {
        int o = excl + local[j];
        g_offset[base + j] = o;
        g_cursor[base + j] = o;
    }
}

// ---------------------------------------------------------------------------
// Phase 3: scatter entries into row-sorted order. Also resolves the token id
// here (subnode_ids is 256 KB -> L2 resident) so the pool phase is lean.
// ---------------------------------------------------------------------------
__global__ void __launch_bounds__(256)
scatter_kernel(const int*   __restrict__ mask_batch,
               const int*   __restrict__ mask_node,
               const int*   __restrict__ mask_subnode,
               const float* __restrict__ mask_values,
               const int*   __restrict__ subnode_ids) {
    int i = blockIdx.x * blockDim.x + threadIdx.x;
    if (i >= NNZ_DIM) return;

    const int   b   = __ldg(mask_batch   + i);
    const int   nd  = __ldg(mask_node    + i);
    const int   s   = __ldg(mask_subnode + i);
    const float v   = __ldg(mask_values  + i);
    const int   tok = __ldg(subnode_ids + b * S_DIM + s);
    const int   row = b * N_DIM + nd;

    int pos = atomicAdd(&g_cursor[row], 1);
    g_sorted[pos] = ((unsigned long long)__float_as_uint(v) << 32)
                  | (unsigned int)tok;
}

// ---------------------------------------------------------------------------
// Phase 4: one warp per output row. Walk the row's CSR segment, gather the
// emb row (coalesced float4 per lane), FMA into registers, single store.
// No atomics anywhere. Double-buffered gather to hide L2 latency.
// ---------------------------------------------------------------------------
__global__ void __launch_bounds__(256)
pool_kernel(const float* __restrict__ emb,    // [VOCAB*D]
            float*       __restrict__ out) {  // [B*N*D]
    const int row  = (blockIdx.x * blockDim.x + threadIdx.x) >> 5;
    const int lane = threadIdx.x & 31;
    if (row >= ROWS) return;

    const int start = g_offset[row];
    const int cnt   = g_count[row];

    const float4* __restrict__ emb4 = reinterpret_cast<const float4*>(emb);

    float ax = 0.f, ay = 0.f, az = 0.f, aw = 0.f;

    if (cnt > 0) {
        // prime the pipeline
        unsigned long long e0 = g_sorted[start];
        int   tok = (int)(unsigned int)e0;
        float v   = __uint_as_float((unsigned int)(e0 >> 32));
        float4 r  = __ldg(emb4 + tok * 32 + lane);

        for (int j = 0; j < cnt; j++) {
            float4 rc = r;
            float  vc = v;
            if (j + 1 < cnt) {
                unsigned long long e = g_sorted[start + j + 1];
                tok = (int)(unsigned int)e;
                v   = __uint_as_float((unsigned int)(e >> 32));
                r   = __ldg(emb4 + tok * 32 + lane);
            }
            ax = fmaf(rc.x, vc, ax);
            ay = fmaf(rc.y, vc, ay);
            az = fmaf(rc.z, vc, az);
            aw = fmaf(rc.w, vc, aw);
        }
    }

    reinterpret_cast<float4*>(out)[row * 32 + lane] =
        make_float4(ax, ay, az, aw);
}

// ---------------------------------------------------------------------------
// Harness entry. Inputs (metadata order):
//   0: subnode_ids  int32  [B,S]
//   1: mask_batch   int32  [NNZ]
//   2: mask_node    int32  [NNZ]
//   3: mask_subnode int32  [NNZ]
//   4: mask_values  fp32   [NNZ]
//   5: emb_table    fp32   [VOCAB,D]
// out: fp32 [B,N,D]
// ---------------------------------------------------------------------------
extern "C" void kernel_launch(void* const* d_in, const int* in_sizes, int n_in,
                              void* d_out, int out_size) {
    const int*   subnode_ids  = (const int*)  d_in[0];
    const int*   mask_batch   = (const int*)  d_in[1];
    const int*   mask_node    = (const int*)  d_in[2];
    const int*   mask_subnode = (const int*)  d_in[3];
    const float* mask_values  = (const float*)d_in[4];
    const float* emb_table    = (const float*)d_in[5];
    float*       out          = (float*)      d_out;

    // Phase 0: reset counters (graph is replayed; must re-zero every call)
    reset_kernel<<<(ROWS + 255) / 256, 256>>>();

    // Phase 1: histogram rows
    hist_kernel<<<NNZ_DIM / 256, 256>>>(mask_batch, mask_node);

    // Phase 2: exclusive scan -> offsets + cursors
    scan_kernel<<<1, 1024>>>();

    // Phase 3: counting-sort entries into row order (tok pre-resolved)
    scatter_kernel<<<NNZ_DIM / 256, 256>>>(mask_batch, mask_node, mask_subnode,
                                           mask_values, subnode_ids);

    // Phase 4: atomic-free per-row gather + accumulate + store
    pool_kernel<<<(ROWS * 32) / 256, 256>>>(emb_table, out);
}